// round 16
// baseline (speedup 1.0000x reference)
#include <cuda_runtime.h>
#include <cuda_bf16.h>
#include <cstdint>

#define N_NODES 50000
#define DIM 128
#define CAP 160                        // bucket slots/node (Poisson(64): P(>160)~1e-24)
#define NTILES ((N_NODES + 127) / 128) // 391

// Scratch (__device__ globals per allocation rules)
__device__ __align__(16) float g_agg[(size_t)N_NODES * DIM];        // agg_mean fp32
__device__ __align__(16) __nv_bfloat16 g_xb[(size_t)N_NODES * DIM]; // x in bf16
__device__ int g_cnt[N_NODES];               // cursor during fill == degree after
__device__ int g_bkt[(size_t)N_NODES * CAP]; // bucketed adjacency (both directions)
__device__ __align__(16) float g_wt[128 * 256]; // WT_cat[n][k] = W*[k][n], tf32-rounded

__device__ __forceinline__ uint32_t tf32_rna(float f) {
    uint32_t r;
    asm("cvt.rna.tf32.f32 %0, %1;" : "=r"(r) : "f"(f));
    return r;
}

// ---------------------------------------------------------------------------
// Convert x -> bf16 scratch (forked stream).
// ---------------------------------------------------------------------------
__global__ void __launch_bounds__(256)
convert_kernel(const float* __restrict__ x) {
    int i = blockIdx.x * blockDim.x + threadIdx.x;
    if (i >= N_NODES * (DIM / 4)) return;
    float4 v = reinterpret_cast<const float4*>(x)[i];
    __nv_bfloat162 lo = __float22bfloat162_rn(make_float2(v.x, v.y));
    __nv_bfloat162 hi = __float22bfloat162_rn(make_float2(v.z, v.w));
    uint2 o;
    o.x = *reinterpret_cast<uint32_t*>(&lo);
    o.y = *reinterpret_cast<uint32_t*>(&hi);
    reinterpret_cast<uint2*>(g_xb)[i] = o;
}

// ---------------------------------------------------------------------------
// Build WT_cat[n][k] = (k<128 ? Wn[k][n] : Ws[k-128][n]), tf32-rounded.
// ---------------------------------------------------------------------------
__global__ void __launch_bounds__(256)
wt_kernel(const float* __restrict__ Wn, const float* __restrict__ Ws) {
    int idx = blockIdx.x * 256 + threadIdx.x;   // 32768 total
    if (idx >= 128 * 256) return;
    int k = idx >> 7;
    int n = idx & 127;
    float v = (k < 128) ? Wn[k * 128 + n] : Ws[(k - 128) * 128 + n];
    g_wt[n * 256 + k] = __uint_as_float(tf32_rna(v));
}

// ---------------------------------------------------------------------------
// Bucket fill with inline dtype detect. At the L2-atomic floor (~48us).
// ---------------------------------------------------------------------------
__device__ __forceinline__ void insert_edge(int s, int d) {
    if ((unsigned)s >= N_NODES || (unsigned)d >= N_NODES) return;
    int ps = atomicAdd(&g_cnt[s], 1);
    if (ps < CAP) g_bkt[(size_t)s * CAP + ps] = d;
    int pd = atomicAdd(&g_cnt[d], 1);
    if (pd < CAP) g_bkt[(size_t)d * CAP + pd] = s;
}

__global__ void __launch_bounds__(256)
fill_kernel(const int* __restrict__ ei32, int n_edges) {
    bool is64 = ((ei32[1] | ei32[3] | ei32[5] | ei32[7]) == 0);  // L1 broadcast
    int e = blockIdx.x * blockDim.x + threadIdx.x;
    if (is64) {
        if (e >= n_edges) return;
        int4 q = reinterpret_cast<const int4*>(ei32)[e];
        insert_edge(q.x, q.z);
    } else {
        int e0 = 2 * e;
        if (e0 >= n_edges) return;
        int4 q = reinterpret_cast<const int4*>(ei32)[e];
        insert_edge(q.x, q.y);
        if (e0 + 1 < n_edges) insert_edge(q.z, q.w);
    }
}

// ---------------------------------------------------------------------------
// Gather-sum: 1 node/warp, uint2/lane, 8-deep MLP, pairwise bf16 HADD2 merge.
// NEW in R16: remainder (<32 neighbors, mean 16 = ~25% of work) now runs its
// full 8-groups through the same 8-deep batched body instead of an MLP=2
// pair loop. Pairing order (j, j+1) preserved -> bit-identical result.
// ---------------------------------------------------------------------------
__device__ __forceinline__ void acc_word(uint32_t w, unsigned long long& acc) {
    uint32_t lo = w << 16;
    uint32_t hi = w & 0xFFFF0000u;
    unsigned long long p;
    asm("mov.b64 %0, {%1, %2};" : "=l"(p) : "r"(lo), "r"(hi));
    asm("add.rn.f32x2 %0, %0, %1;" : "+l"(acc) : "l"(p));
}
__device__ __forceinline__ uint32_t hadd2_bits(uint32_t a, uint32_t b) {
    __nv_bfloat162 x = *reinterpret_cast<__nv_bfloat162*>(&a);
    __nv_bfloat162 y = *reinterpret_cast<__nv_bfloat162*>(&b);
    __nv_bfloat162 r = __hadd2(x, y);
    return *reinterpret_cast<uint32_t*>(&r);
}
__device__ __forceinline__ float2 unpack_f32x2(unsigned long long v) {
    uint32_t lo, hi;
    asm("mov.b64 {%0, %1}, %2;" : "=r"(lo), "=r"(hi) : "l"(v));
    return make_float2(__uint_as_float(lo), __uint_as_float(hi));
}

__global__ void __launch_bounds__(256)
gather_kernel() {
    int node = (blockIdx.x * blockDim.x + threadIdx.x) >> 5;
    int lane = threadIdx.x & 31;
    if (node >= N_NODES) return;

    int deg = g_cnt[node];
    int m = (deg < CAP) ? deg : CAP;

    const uint2* __restrict__ xb  = reinterpret_cast<const uint2*>(g_xb);
    const int*   __restrict__ bkt = g_bkt + (size_t)node * CAP;

    unsigned long long a0 = 0ull, a1 = 0ull;

    int i = 0;
    for (; i + 32 <= m; i += 32) {
        int myidx = bkt[i + lane];
#pragma unroll
        for (int h = 0; h < 4; h++) {
            uint2 v[8];
#pragma unroll
            for (int u = 0; u < 8; u++) {
                int n = __shfl_sync(0xffffffffu, myidx, h * 8 + u);
                v[u] = xb[(size_t)n * 32 + lane];
            }
#pragma unroll
            for (int p = 0; p < 4; p++) {   // merge neighbor pairs in bf16
                uint32_t mx = hadd2_bits(v[2 * p].x, v[2 * p + 1].x);
                uint32_t my = hadd2_bits(v[2 * p].y, v[2 * p + 1].y);
                acc_word(mx, a0);
                acc_word(my, a1);
            }
        }
    }
    int rem = m - i;
    if (rem > 0) {
        int myidx = (lane < rem) ? bkt[i + lane] : 0;
        int j = 0;
        // full 8-groups of the remainder: same 8-deep batched body
        for (; j + 8 <= rem; j += 8) {
            uint2 v[8];
#pragma unroll
            for (int u = 0; u < 8; u++) {
                int n = __shfl_sync(0xffffffffu, myidx, j + u);
                v[u] = xb[(size_t)n * 32 + lane];
            }
#pragma unroll
            for (int p = 0; p < 4; p++) {
                uint32_t mx = hadd2_bits(v[2 * p].x, v[2 * p + 1].x);
                uint32_t my = hadd2_bits(v[2 * p].y, v[2 * p + 1].y);
                acc_word(mx, a0);
                acc_word(my, a1);
            }
        }
        // last <8: pairs, then single
        for (; j + 2 <= rem; j += 2) {
            int n0 = __shfl_sync(0xffffffffu, myidx, j);
            int n1 = __shfl_sync(0xffffffffu, myidx, j + 1);
            uint2 v0 = xb[(size_t)n0 * 32 + lane];
            uint2 v1 = xb[(size_t)n1 * 32 + lane];
            acc_word(hadd2_bits(v0.x, v1.x), a0);
            acc_word(hadd2_bits(v0.y, v1.y), a1);
        }
        if (j < rem) {
            int n = __shfl_sync(0xffffffffu, myidx, j);
            uint2 v = xb[(size_t)n * 32 + lane];
            acc_word(v.x, a0);
            acc_word(v.y, a1);
        }
    }

    float inv = 1.0f / fmaxf((float)deg, 1.0f);
    float2 f0 = unpack_f32x2(a0), f1 = unpack_f32x2(a1);
    float4 r = make_float4(f0.x * inv, f0.y * inv, f1.x * inv, f1.y * inv);
    reinterpret_cast<float4*>(g_agg)[(size_t)node * 32 + lane] = r;
}

// ---------------------------------------------------------------------------
// Fused GEMM via mma.sync tf32: out = [agg | x] @ WT_cat^T + b.
// CTA 256 thr, tile 128x128, K=256 in 8 smem chunks; warp tile 32x64.
// ---------------------------------------------------------------------------
#define SMEM_STRIDE 36

__device__ __forceinline__ void mma_tf32(float* c, uint32_t a0, uint32_t a1,
                                         uint32_t a2, uint32_t a3,
                                         uint32_t b0, uint32_t b1) {
    asm volatile(
        "mma.sync.aligned.m16n8k8.row.col.f32.tf32.tf32.f32 "
        "{%0,%1,%2,%3}, {%4,%5,%6,%7}, {%8,%9}, {%0,%1,%2,%3};"
        : "+f"(c[0]), "+f"(c[1]), "+f"(c[2]), "+f"(c[3])
        : "r"(a0), "r"(a1), "r"(a2), "r"(a3), "r"(b0), "r"(b1));
}

__global__ void __launch_bounds__(256)
fused_gemm_kernel(const float* __restrict__ x,
                  const float* __restrict__ bias,
                  float* __restrict__ out) {
    __shared__ float sA[128][SMEM_STRIDE];
    __shared__ float sB[128][SMEM_STRIDE];

    int tid  = threadIdx.x;
    int w    = tid >> 5;
    int lane = tid & 31;
    int g    = lane >> 2;
    int tig  = lane & 3;
    int tile = blockIdx.x;

    int wr = (w & 3) * 32;
    int wc = (w >> 2) * 64;

    float acc[2][8][4];
#pragma unroll
    for (int mi = 0; mi < 2; mi++)
#pragma unroll
        for (int nf = 0; nf < 8; nf++)
#pragma unroll
            for (int q = 0; q < 4; q++) acc[mi][nf][q] = 0.f;

    for (int ch = 0; ch < 8; ch++) {
        int k0 = ch * 32;
#pragma unroll
        for (int it = 0; it < 4; it++) {
            int idx = tid + 256 * it;
            int row = idx >> 3;
            int j   = idx & 7;
            int grow = tile * 128 + row;
            int arow = (grow < N_NODES) ? grow : (N_NODES - 1);
            const float* src = (k0 < 128)
                ? (g_agg + (size_t)arow * DIM + k0)
                : (x     + (size_t)arow * DIM + (k0 - 128));
            float4 v = *reinterpret_cast<const float4*>(src + j * 4);
            sA[row][j * 4 + 0] = __uint_as_float(tf32_rna(v.x));
            sA[row][j * 4 + 1] = __uint_as_float(tf32_rna(v.y));
            sA[row][j * 4 + 2] = __uint_as_float(tf32_rna(v.z));
            sA[row][j * 4 + 3] = __uint_as_float(tf32_rna(v.w));
        }
#pragma unroll
        for (int it = 0; it < 4; it++) {
            int idx = tid + 256 * it;
            int n = idx >> 3;
            int j = idx & 7;
            float4 v = *reinterpret_cast<const float4*>(g_wt + (size_t)n * 256 + k0 + j * 4);
            *reinterpret_cast<float4*>(&sB[n][j * 4]) = v;
        }
        __syncthreads();

#pragma unroll
        for (int ks = 0; ks < 32; ks += 8) {
            uint32_t a[2][4];
#pragma unroll
            for (int mi = 0; mi < 2; mi++) {
                int r = wr + 16 * mi + g;
                a[mi][0] = __float_as_uint(sA[r][ks + tig]);
                a[mi][1] = __float_as_uint(sA[r + 8][ks + tig]);
                a[mi][2] = __float_as_uint(sA[r][ks + tig + 4]);
                a[mi][3] = __float_as_uint(sA[r + 8][ks + tig + 4]);
            }
#pragma unroll
            for (int nf = 0; nf < 8; nf++) {
                int n = wc + 8 * nf + g;
                uint32_t b0 = __float_as_uint(sB[n][ks + tig]);
                uint32_t b1 = __float_as_uint(sB[n][ks + tig + 4]);
                mma_tf32(acc[0][nf], a[0][0], a[0][1], a[0][2], a[0][3], b0, b1);
                mma_tf32(acc[1][nf], a[1][0], a[1][1], a[1][2], a[1][3], b0, b1);
            }
        }
        __syncthreads();
    }

#pragma unroll
    for (int mi = 0; mi < 2; mi++) {
        int row0 = tile * 128 + wr + 16 * mi + g;
#pragma unroll
        for (int nf = 0; nf < 8; nf++) {
            int c = wc + 8 * nf + 2 * tig;
            float2 bz = *reinterpret_cast<const float2*>(bias + c);
            if (row0 < N_NODES) {
                float2 o = make_float2(acc[mi][nf][0] + bz.x, acc[mi][nf][1] + bz.y);
                *reinterpret_cast<float2*>(out + (size_t)row0 * DIM + c) = o;
            }
            if (row0 + 8 < N_NODES) {
                float2 o = make_float2(acc[mi][nf][2] + bz.x, acc[mi][nf][3] + bz.y);
                *reinterpret_cast<float2*>(out + (size_t)(row0 + 8) * DIM + c) = o;
            }
        }
    }
}

// ---------------------------------------------------------------------------
// Launch (R10 graph — best measured):
// s2:   convert(x->bf16) [eCvt] -> wt transpose [eWT]
// main: memset(cnt) -> fill -> [wait eCvt] gather -> [wait eWT] fused gemm
// ---------------------------------------------------------------------------
extern "C" void kernel_launch(void* const* d_in, const int* in_sizes, int n_in,
                              void* d_out, int out_size) {
    const float* x    = (const float*)d_in[0];
    const int*   ei32 = (const int*)d_in[1];
    const float* Wn   = (const float*)d_in[2];
    const float* Ws   = (const float*)d_in[3];
    const float* bias = (const float*)d_in[4];
    float* out = (float*)d_out;

    int n_edges = in_sizes[1] / 2;

    void* cnt_ptr = nullptr;
    cudaGetSymbolAddress(&cnt_ptr, g_cnt);

    cudaStream_t s2;
    cudaStreamCreateWithFlags(&s2, cudaStreamNonBlocking);
    cudaEvent_t eFork, eCvt, eWT;
    cudaEventCreateWithFlags(&eFork, cudaEventDisableTiming);
    cudaEventCreateWithFlags(&eCvt,  cudaEventDisableTiming);
    cudaEventCreateWithFlags(&eWT,   cudaEventDisableTiming);

    cudaEventRecord(eFork, 0);
    cudaStreamWaitEvent(s2, eFork, 0);

    int n4 = N_NODES * (DIM / 4);
    convert_kernel<<<(n4 + 255) / 256, 256, 0, s2>>>(x);
    cudaEventRecord(eCvt, s2);
    wt_kernel<<<128, 256, 0, s2>>>(Wn, Ws);
    cudaEventRecord(eWT, s2);

    cudaMemsetAsync(cnt_ptr, 0, (size_t)N_NODES * sizeof(int));
    fill_kernel<<<(n_edges + 255) / 256, 256>>>(ei32, n_edges);

    cudaStreamWaitEvent(0, eCvt, 0);
    gather_kernel<<<(N_NODES * 32 + 255) / 256, 256>>>();

    cudaStreamWaitEvent(0, eWT, 0);
    fused_gemm_kernel<<<NTILES, 256>>>(x, bias, out);

    // Handles intentionally not destroyed mid-capture (host-side only).
}

// round 17
// speedup vs baseline: 1.0939x; 1.0939x over previous
#include <cuda_runtime.h>
#include <cuda_bf16.h>
#include <cstdint>

#define N_NODES 50000
#define DIM 128
#define CAP 160                        // bucket slots/node (Poisson(64): P(>160)~1e-24)
#define NTILES ((N_NODES + 127) / 128) // 391

// Scratch (__device__ globals per allocation rules)
__device__ __align__(16) float g_agg[(size_t)N_NODES * DIM];        // agg_mean fp32
__device__ __align__(16) __nv_bfloat16 g_xb[(size_t)N_NODES * DIM]; // x in bf16
__device__ int g_cnt[N_NODES];               // cursor during fill == degree after
__device__ int g_bkt[(size_t)N_NODES * CAP]; // bucketed adjacency (both directions)
__device__ __align__(16) float g_wt[128 * 256]; // WT_cat[n][k] = W*[k][n], tf32-rounded

__device__ __forceinline__ uint32_t tf32_rna(float f) {
    uint32_t r;
    asm("cvt.rna.tf32.f32 %0, %1;" : "=r"(r) : "f"(f));
    return r;
}

// ---------------------------------------------------------------------------
// Convert x -> bf16 scratch (forked stream).
// ---------------------------------------------------------------------------
__global__ void __launch_bounds__(256)
convert_kernel(const float* __restrict__ x) {
    int i = blockIdx.x * blockDim.x + threadIdx.x;
    if (i >= N_NODES * (DIM / 4)) return;
    float4 v = reinterpret_cast<const float4*>(x)[i];
    __nv_bfloat162 lo = __float22bfloat162_rn(make_float2(v.x, v.y));
    __nv_bfloat162 hi = __float22bfloat162_rn(make_float2(v.z, v.w));
    uint2 o;
    o.x = *reinterpret_cast<uint32_t*>(&lo);
    o.y = *reinterpret_cast<uint32_t*>(&hi);
    reinterpret_cast<uint2*>(g_xb)[i] = o;
}

// ---------------------------------------------------------------------------
// Build WT_cat[n][k] = (k<128 ? Wn[k][n] : Ws[k-128][n]), tf32-rounded.
// ---------------------------------------------------------------------------
__global__ void __launch_bounds__(256)
wt_kernel(const float* __restrict__ Wn, const float* __restrict__ Ws) {
    int idx = blockIdx.x * 256 + threadIdx.x;   // 32768 total
    if (idx >= 128 * 256) return;
    int k = idx >> 7;
    int n = idx & 127;
    float v = (k < 128) ? Wn[k * 128 + n] : Ws[(k - 128) * 128 + n];
    g_wt[n * 256 + k] = __uint_as_float(tf32_rna(v));
}

// ---------------------------------------------------------------------------
// Bucket fill with inline dtype detect. At the L2-atomic floor (~48us).
// ---------------------------------------------------------------------------
__device__ __forceinline__ void insert_edge(int s, int d) {
    if ((unsigned)s >= N_NODES || (unsigned)d >= N_NODES) return;
    int ps = atomicAdd(&g_cnt[s], 1);
    if (ps < CAP) g_bkt[(size_t)s * CAP + ps] = d;
    int pd = atomicAdd(&g_cnt[d], 1);
    if (pd < CAP) g_bkt[(size_t)d * CAP + pd] = s;
}

__global__ void __launch_bounds__(256)
fill_kernel(const int* __restrict__ ei32, int n_edges) {
    bool is64 = ((ei32[1] | ei32[3] | ei32[5] | ei32[7]) == 0);  // L1 broadcast
    int e = blockIdx.x * blockDim.x + threadIdx.x;
    if (is64) {
        if (e >= n_edges) return;
        int4 q = reinterpret_cast<const int4*>(ei32)[e];
        insert_edge(q.x, q.z);
    } else {
        int e0 = 2 * e;
        if (e0 >= n_edges) return;
        int4 q = reinterpret_cast<const int4*>(ei32)[e];
        insert_edge(q.x, q.y);
        if (e0 + 1 < n_edges) insert_edge(q.z, q.w);
    }
}

// ---------------------------------------------------------------------------
// Gather-sum (R16 body, reproduced 59.2us — at floor): 1 node/warp,
// uint2/lane, 8-deep MLP, pairwise bf16 HADD2 merge, f32x2 accumulate.
// ---------------------------------------------------------------------------
__device__ __forceinline__ void acc_word(uint32_t w, unsigned long long& acc) {
    uint32_t lo = w << 16;
    uint32_t hi = w & 0xFFFF0000u;
    unsigned long long p;
    asm("mov.b64 %0, {%1, %2};" : "=l"(p) : "r"(lo), "r"(hi));
    asm("add.rn.f32x2 %0, %0, %1;" : "+l"(acc) : "l"(p));
}
__device__ __forceinline__ uint32_t hadd2_bits(uint32_t a, uint32_t b) {
    __nv_bfloat162 x = *reinterpret_cast<__nv_bfloat162*>(&a);
    __nv_bfloat162 y = *reinterpret_cast<__nv_bfloat162*>(&b);
    __nv_bfloat162 r = __hadd2(x, y);
    return *reinterpret_cast<uint32_t*>(&r);
}
__device__ __forceinline__ float2 unpack_f32x2(unsigned long long v) {
    uint32_t lo, hi;
    asm("mov.b64 {%0, %1}, %2;" : "=r"(lo), "=r"(hi) : "l"(v));
    return make_float2(__uint_as_float(lo), __uint_as_float(hi));
}

__global__ void __launch_bounds__(256)
gather_kernel() {
    int node = (blockIdx.x * blockDim.x + threadIdx.x) >> 5;
    int lane = threadIdx.x & 31;
    if (node >= N_NODES) return;

    int deg = g_cnt[node];
    int m = (deg < CAP) ? deg : CAP;

    const uint2* __restrict__ xb  = reinterpret_cast<const uint2*>(g_xb);
    const int*   __restrict__ bkt = g_bkt + (size_t)node * CAP;

    unsigned long long a0 = 0ull, a1 = 0ull;

    int i = 0;
    for (; i + 32 <= m; i += 32) {
        int myidx = bkt[i + lane];
#pragma unroll
        for (int h = 0; h < 4; h++) {
            uint2 v[8];
#pragma unroll
            for (int u = 0; u < 8; u++) {
                int n = __shfl_sync(0xffffffffu, myidx, h * 8 + u);
                v[u] = xb[(size_t)n * 32 + lane];
            }
#pragma unroll
            for (int p = 0; p < 4; p++) {
                uint32_t mx = hadd2_bits(v[2 * p].x, v[2 * p + 1].x);
                uint32_t my = hadd2_bits(v[2 * p].y, v[2 * p + 1].y);
                acc_word(mx, a0);
                acc_word(my, a1);
            }
        }
    }
    int rem = m - i;
    if (rem > 0) {
        int myidx = (lane < rem) ? bkt[i + lane] : 0;
        int j = 0;
        for (; j + 8 <= rem; j += 8) {
            uint2 v[8];
#pragma unroll
            for (int u = 0; u < 8; u++) {
                int n = __shfl_sync(0xffffffffu, myidx, j + u);
                v[u] = xb[(size_t)n * 32 + lane];
            }
#pragma unroll
            for (int p = 0; p < 4; p++) {
                uint32_t mx = hadd2_bits(v[2 * p].x, v[2 * p + 1].x);
                uint32_t my = hadd2_bits(v[2 * p].y, v[2 * p + 1].y);
                acc_word(mx, a0);
                acc_word(my, a1);
            }
        }
        for (; j + 2 <= rem; j += 2) {
            int n0 = __shfl_sync(0xffffffffu, myidx, j);
            int n1 = __shfl_sync(0xffffffffu, myidx, j + 1);
            uint2 v0 = xb[(size_t)n0 * 32 + lane];
            uint2 v1 = xb[(size_t)n1 * 32 + lane];
            acc_word(hadd2_bits(v0.x, v1.x), a0);
            acc_word(hadd2_bits(v0.y, v1.y), a1);
        }
        if (j < rem) {
            int n = __shfl_sync(0xffffffffu, myidx, j);
            uint2 v = xb[(size_t)n * 32 + lane];
            acc_word(v.x, a0);
            acc_word(v.y, a1);
        }
    }

    float inv = 1.0f / fmaxf((float)deg, 1.0f);
    float2 f0 = unpack_f32x2(a0), f1 = unpack_f32x2(a1);
    float4 r = make_float4(f0.x * inv, f0.y * inv, f1.x * inv, f1.y * inv);
    reinterpret_cast<float4*>(g_agg)[(size_t)node * 32 + lane] = r;
}

// ---------------------------------------------------------------------------
// Fused GEMM v2: cp.async double-buffered pipeline.
// out = [agg | x] @ WT_cat^T + b. CTA 256 thr, tile 128x128, K=256 in 8
// chunks of 32; chunk ch+2 streams in (LDGSTS, L1-bypass) while ch computes.
// A is raw fp32 (HMMA.TF32 truncates low mantissa bits); B pre-rounded rna.
// Dynamic smem: 2 x (sA + sB) = 72KB; 391 CTAs = one wave at 3 CTAs/SM.
// ---------------------------------------------------------------------------
#define SMEM_STRIDE 36
#define BUF_FLOATS (128 * SMEM_STRIDE)          // one tile buffer
#define GEMM_SMEM_BYTES (4 * BUF_FLOATS * 4)    // sA[2] + sB[2] = 73728 B

#define CP_ASYNC16(dst, src) \
    asm volatile("cp.async.cg.shared.global [%0], [%1], 16;" \
                 :: "r"(dst), "l"(src) : "memory")
#define CP_COMMIT() asm volatile("cp.async.commit_group;" ::: "memory")
#define CP_WAIT1()  asm volatile("cp.async.wait_group 1;" ::: "memory")
#define CP_WAIT0()  asm volatile("cp.async.wait_group 0;" ::: "memory")

__device__ __forceinline__ void mma_tf32(float* c, uint32_t a0, uint32_t a1,
                                         uint32_t a2, uint32_t a3,
                                         uint32_t b0, uint32_t b1) {
    asm volatile(
        "mma.sync.aligned.m16n8k8.row.col.f32.tf32.tf32.f32 "
        "{%0,%1,%2,%3}, {%4,%5,%6,%7}, {%8,%9}, {%0,%1,%2,%3};"
        : "+f"(c[0]), "+f"(c[1]), "+f"(c[2]), "+f"(c[3])
        : "r"(a0), "r"(a1), "r"(a2), "r"(a3), "r"(b0), "r"(b1));
}

__global__ void __launch_bounds__(256)
fused_gemm_kernel(const float* __restrict__ x,
                  const float* __restrict__ bias,
                  float* __restrict__ out) {
    extern __shared__ float smem[];
    // layout: sA0 | sA1 | sB0 | sB1
    float* sAbuf[2] = { smem,                smem + BUF_FLOATS };
    float* sBbuf[2] = { smem + 2 * BUF_FLOATS, smem + 3 * BUF_FLOATS };

    int tid  = threadIdx.x;
    int w    = tid >> 5;
    int lane = tid & 31;
    int g    = lane >> 2;
    int tig  = lane & 3;
    int tile = blockIdx.x;

    int wr = (w & 3) * 32;
    int wc = (w >> 2) * 64;

    // fixed per-thread staging coords: j = tid&7, rows r0+32*it
    int jstage = tid & 7;
    int r0     = tid >> 3;

    float acc[2][8][4];
#pragma unroll
    for (int mi = 0; mi < 2; mi++)
#pragma unroll
        for (int nf = 0; nf < 8; nf++)
#pragma unroll
            for (int q = 0; q < 4; q++) acc[mi][nf][q] = 0.f;

    // --- staging helper (inlined twice below via macro-ish lambda) ---
    auto stage = [&](int ch, int b) {
        int k0 = ch * 32;
#pragma unroll
        for (int it = 0; it < 4; it++) {
            int row  = r0 + 32 * it;
            int grow = tile * 128 + row;
            int arow = (grow < N_NODES) ? grow : (N_NODES - 1);
            const float* asrc = (k0 < 128)
                ? (g_agg + (size_t)arow * DIM + k0 + jstage * 4)
                : (x     + (size_t)arow * DIM + (k0 - 128) + jstage * 4);
            uint32_t da = (uint32_t)__cvta_generic_to_shared(
                &sAbuf[b][row * SMEM_STRIDE + jstage * 4]);
            CP_ASYNC16(da, asrc);
            const float* bsrc = g_wt + (size_t)row * 256 + k0 + jstage * 4;
            uint32_t db = (uint32_t)__cvta_generic_to_shared(
                &sBbuf[b][row * SMEM_STRIDE + jstage * 4]);
            CP_ASYNC16(db, bsrc);
        }
        CP_COMMIT();
    };

    stage(0, 0);
    stage(1, 1);

    for (int ch = 0; ch < 8; ch++) {
        int b = ch & 1;
        if (ch == 7) { CP_WAIT0(); } else { CP_WAIT1(); }
        __syncthreads();

        const float* A = sAbuf[b];
        const float* B = sBbuf[b];
#pragma unroll
        for (int ks = 0; ks < 32; ks += 8) {
            uint32_t a[2][4];
#pragma unroll
            for (int mi = 0; mi < 2; mi++) {
                int r = wr + 16 * mi + g;
                a[mi][0] = __float_as_uint(A[r * SMEM_STRIDE + ks + tig]);
                a[mi][1] = __float_as_uint(A[(r + 8) * SMEM_STRIDE + ks + tig]);
                a[mi][2] = __float_as_uint(A[r * SMEM_STRIDE + ks + tig + 4]);
                a[mi][3] = __float_as_uint(A[(r + 8) * SMEM_STRIDE + ks + tig + 4]);
            }
#pragma unroll
            for (int nf = 0; nf < 8; nf++) {
                int n = wc + 8 * nf + g;
                uint32_t b0 = __float_as_uint(B[n * SMEM_STRIDE + ks + tig]);
                uint32_t b1 = __float_as_uint(B[n * SMEM_STRIDE + ks + tig + 4]);
                mma_tf32(acc[0][nf], a[0][0], a[0][1], a[0][2], a[0][3], b0, b1);
                mma_tf32(acc[1][nf], a[1][0], a[1][1], a[1][2], a[1][3], b0, b1);
            }
        }
        __syncthreads();
        if (ch + 2 < 8) stage(ch + 2, b);
    }

    // --- epilogue ---
#pragma unroll
    for (int mi = 0; mi < 2; mi++) {
        int row0 = tile * 128 + wr + 16 * mi + g;
#pragma unroll
        for (int nf = 0; nf < 8; nf++) {
            int c = wc + 8 * nf + 2 * tig;
            float2 bz = *reinterpret_cast<const float2*>(bias + c);
            if (row0 < N_NODES) {
                float2 o = make_float2(acc[mi][nf][0] + bz.x, acc[mi][nf][1] + bz.y);
                *reinterpret_cast<float2*>(out + (size_t)row0 * DIM + c) = o;
            }
            if (row0 + 8 < N_NODES) {
                float2 o = make_float2(acc[mi][nf][2] + bz.x, acc[mi][nf][3] + bz.y);
                *reinterpret_cast<float2*>(out + (size_t)(row0 + 8) * DIM + c) = o;
            }
        }
    }
}

// ---------------------------------------------------------------------------
// Launch (R10 graph — best measured):
// s2:   convert(x->bf16) [eCvt] -> wt transpose [eWT]
// main: memset(cnt) -> fill -> [wait eCvt] gather -> [wait eWT] fused gemm
// ---------------------------------------------------------------------------
extern "C" void kernel_launch(void* const* d_in, const int* in_sizes, int n_in,
                              void* d_out, int out_size) {
    const float* x    = (const float*)d_in[0];
    const int*   ei32 = (const int*)d_in[1];
    const float* Wn   = (const float*)d_in[2];
    const float* Ws   = (const float*)d_in[3];
    const float* bias = (const float*)d_in[4];
    float* out = (float*)d_out;

    int n_edges = in_sizes[1] / 2;

    void* cnt_ptr = nullptr;
    cudaGetSymbolAddress(&cnt_ptr, g_cnt);

    cudaFuncSetAttribute(fused_gemm_kernel,
                         cudaFuncAttributeMaxDynamicSharedMemorySize,
                         GEMM_SMEM_BYTES);

    cudaStream_t s2;
    cudaStreamCreateWithFlags(&s2, cudaStreamNonBlocking);
    cudaEvent_t eFork, eCvt, eWT;
    cudaEventCreateWithFlags(&eFork, cudaEventDisableTiming);
    cudaEventCreateWithFlags(&eCvt,  cudaEventDisableTiming);
    cudaEventCreateWithFlags(&eWT,   cudaEventDisableTiming);

    cudaEventRecord(eFork, 0);
    cudaStreamWaitEvent(s2, eFork, 0);

    int n4 = N_NODES * (DIM / 4);
    convert_kernel<<<(n4 + 255) / 256, 256, 0, s2>>>(x);
    cudaEventRecord(eCvt, s2);
    wt_kernel<<<128, 256, 0, s2>>>(Wn, Ws);
    cudaEventRecord(eWT, s2);

    cudaMemsetAsync(cnt_ptr, 0, (size_t)N_NODES * sizeof(int));
    fill_kernel<<<(n_edges + 255) / 256, 256>>>(ei32, n_edges);

    cudaStreamWaitEvent(0, eCvt, 0);
    gather_kernel<<<(N_NODES * 32 + 255) / 256, 256>>>();

    cudaStreamWaitEvent(0, eWT, 0);
    fused_gemm_kernel<<<NTILES, 256, GEMM_SMEM_BYTES>>>(x, bias, out);

    // Handles intentionally not destroyed mid-capture (host-side only).
}